// round 11
// baseline (speedup 1.0000x reference)
#include <cuda_runtime.h>

#define B_   2
#define S_   2048
#define H_   16
#define HD_  64
#define DIM_ 1024
#define SCALE_ 0.125f

// Scratch (allocation-free rule: __device__ globals)
__device__ float g_qkv[(size_t)B_ * S_ * 3 * DIM_];   // 50.3 MB
__device__ float g_attn[(size_t)B_ * S_ * DIM_];      // 16.8 MB

__device__ __forceinline__ unsigned f2tf(float x) {
    unsigned r;
    asm("cvt.rna.tf32.f32 %0, %1;" : "=r"(r) : "f"(x));
    return r;
}
__device__ __forceinline__ float tff(float x) {
    return __uint_as_float(f2tf(x));
}

#define MMA_TF32(c, a, b)                                                  \
    asm volatile("mma.sync.aligned.m16n8k8.row.col.f32.tf32.tf32.f32 "     \
                 "{%0,%1,%2,%3}, {%4,%5,%6,%7}, {%8,%9}, {%0,%1,%2,%3};"   \
                 : "+f"(c[0]), "+f"(c[1]), "+f"(c[2]), "+f"(c[3])          \
                 : "r"(a[0]), "r"(a[1]), "r"(a[2]), "r"(a[3]),             \
                   "r"(b[0]), "r"(b[1]))

// ---------------------------------------------------------------------------
// TF32 tensor-core GEMM v2 (unchanged from R10): 128x128 tile, BK=16,
// 8 warps, k-pair packed smem, 2-stage double buffer.
// ---------------------------------------------------------------------------
#define P_ST 132

__global__ void __launch_bounds__(256, 2) tgemm128_kernel(
    const float* __restrict__ A, const float* __restrict__ Bm,
    float* __restrict__ C, int M, int N, int K)
{
    __shared__ float2 As2[2][8 * P_ST];
    __shared__ float2 Bs2[2][8 * P_ST];

    const int tid  = threadIdx.x;
    const int lane = tid & 31;
    const int warp = tid >> 5;
    const int g    = lane >> 2;
    const int t    = lane & 3;
    const int wm   = (warp & 1) * 64;
    const int wn   = (warp >> 1) * 32;
    const int bm   = blockIdx.y * 128;
    const int bn   = blockIdx.x * 128;

    const int am = tid >> 1;
    const int ah = tid & 1;
    const int kk6 = tid >> 5;
    const int kk  = ((kk6 >> 2) << 3) + (kk6 & 3);
    const int n4  = (tid & 31) << 2;

    const float* Arow = A + (size_t)(bm + am) * K + 8 * ah;
    const float* Bb   = Bm + bn + n4;

    float c[4][4][4];
    #pragma unroll
    for (int mi = 0; mi < 4; mi++)
        #pragma unroll
        for (int ni = 0; ni < 4; ni++)
            #pragma unroll
            for (int r = 0; r < 4; r++) c[mi][ni][r] = 0.f;

    float4 ra0, ra1, rb0, rb1;

    ra0 = *(const float4*)&Arow[0];
    ra1 = *(const float4*)&Arow[4];
    rb0 = *(const float4*)&Bb[(size_t)kk * N];
    rb1 = *(const float4*)&Bb[(size_t)(kk + 4) * N];

    {
        float a0[4] = {ra0.x, ra0.y, ra0.z, ra0.w};
        float a1[4] = {ra1.x, ra1.y, ra1.z, ra1.w};
        #pragma unroll
        for (int j = 0; j < 4; j++)
            As2[0][(4 * ah + j) * P_ST + am] = make_float2(tff(a0[j]), tff(a1[j]));
        float b0[4] = {rb0.x, rb0.y, rb0.z, rb0.w};
        float b1[4] = {rb1.x, rb1.y, rb1.z, rb1.w};
        #pragma unroll
        for (int j = 0; j < 4; j++)
            Bs2[0][kk6 * P_ST + n4 + j] = make_float2(tff(b0[j]), tff(b1[j]));
    }
    __syncthreads();

    int s = 0;
    for (int k0 = 0; k0 < K; k0 += 16) {
        const bool has_next = (k0 + 16 < K);
        if (has_next) {
            ra0 = *(const float4*)&Arow[k0 + 16];
            ra1 = *(const float4*)&Arow[k0 + 20];
            rb0 = *(const float4*)&Bb[(size_t)(k0 + 16 + kk) * N];
            rb1 = *(const float4*)&Bb[(size_t)(k0 + 20 + kk) * N];
        }

        #pragma unroll
        for (int ks = 0; ks < 2; ks++) {
            const int pb = 4 * ks + t;
            unsigned a[4][4], b[4][2];
            #pragma unroll
            for (int mi = 0; mi < 4; mi++) {
                int m0 = wm + mi * 16 + g;
                float2 v  = As2[s][pb * P_ST + m0];
                float2 v2 = As2[s][pb * P_ST + m0 + 8];
                a[mi][0] = __float_as_uint(v.x);
                a[mi][1] = __float_as_uint(v2.x);
                a[mi][2] = __float_as_uint(v.y);
                a[mi][3] = __float_as_uint(v2.y);
            }
            #pragma unroll
            for (int ni = 0; ni < 4; ni++) {
                int n0 = wn + ni * 8 + g;
                float2 w = Bs2[s][pb * P_ST + n0];
                b[ni][0] = __float_as_uint(w.x);
                b[ni][1] = __float_as_uint(w.y);
            }
            #pragma unroll
            for (int mi = 0; mi < 4; mi++)
                #pragma unroll
                for (int ni = 0; ni < 4; ni++)
                    MMA_TF32(c[mi][ni], a[mi], b[ni]);
        }

        if (has_next) {
            float a0[4] = {ra0.x, ra0.y, ra0.z, ra0.w};
            float a1[4] = {ra1.x, ra1.y, ra1.z, ra1.w};
            #pragma unroll
            for (int j = 0; j < 4; j++)
                As2[s ^ 1][(4 * ah + j) * P_ST + am] = make_float2(tff(a0[j]), tff(a1[j]));
            float b0[4] = {rb0.x, rb0.y, rb0.z, rb0.w};
            float b1[4] = {rb1.x, rb1.y, rb1.z, rb1.w};
            #pragma unroll
            for (int j = 0; j < 4; j++)
                Bs2[s ^ 1][kk6 * P_ST + n4 + j] = make_float2(tff(b0[j]), tff(b1[j]));
            __syncthreads();
        }
        s ^= 1;
    }

    #pragma unroll
    for (int mi = 0; mi < 4; mi++) {
        int row = bm + wm + mi * 16 + g;
        #pragma unroll
        for (int ni = 0; ni < 4; ni++) {
            int col = bn + wn + ni * 8 + 2 * t;
            *(float2*)&C[(size_t)row * N + col] =
                make_float2(c[mi][ni][0], c[mi][ni][1]);
            *(float2*)&C[(size_t)(row + 8) * N + col] =
                make_float2(c[mi][ni][2], c[mi][ni][3]);
        }
    }
}

// ---------------------------------------------------------------------------
// Flash attention v4: tf32 MMAs with k-pair packed float2 smem.
//   Ks2[key][4ks+t]        = (K[key][8ks+t],   K[key][8ks+t+4])   stride 37 f2
//   Vs2[4ks+t][hd]         = (V[8ks+t][hd],    V[8ks+t+4][hd])    stride 68 f2
//   Pw2[k][g] (per warp)   = (P[g][k],         P[g+8][k])         stride 12 f2
// QK b-frag: 1 LDS.64; PV b-frag: 1 LDS.64; pa-frag: 2 LDS.64.
// All fragment access patterns <= 2-way on 64-bit (free).
// ---------------------------------------------------------------------------
#define KS2 37
#define VS2 68
#define PS2 12
#define KS2_SZ (64 * KS2)
#define VS2_SZ (32 * VS2)
#define PS2_SZ (64 * PS2)
#define FL_SMEM ((KS2_SZ + VS2_SZ + 8 * PS2_SZ) * 8)   // 85504 B

__global__ void __launch_bounds__(256) flash4_kernel()
{
    extern __shared__ float2 sm2[];
    float2* Ks2 = sm2;
    float2* Vs2 = sm2 + KS2_SZ;
    float2* Pa  = sm2 + KS2_SZ + VS2_SZ;    // 8 warp strips

    const int tid  = threadIdx.x;
    const int lane = tid & 31;
    const int warp = tid >> 5;
    const int g    = lane >> 2;
    const int t    = lane & 3;
    const int wm   = warp << 4;
    const int qb   = blockIdx.x;
    const int h    = blockIdx.y;
    const int b    = blockIdx.z;

    float2* Pw2 = Pa + warp * PS2_SZ;

    // loader mappings
    const int krr = tid >> 3;            // K row 0..31 (+32 for i=1)
    const int kc8 = (tid & 7) << 3;      // K col group
    const int vpr = tid >> 4;            // V pair-row 0..15 (+16 for i=1)
    const int vc4 = (tid & 15) << 2;     // V col group

    // --- Q fragments in registers (tf32, scale folded) ---
    unsigned qa[8][4];
    {
        const float* q0 = g_qkv + ((size_t)(b * S_ + qb * 128 + wm + g) * 3) * DIM_ + h * HD_;
        const float* q1 = q0 + (size_t)8 * 3 * DIM_;
        #pragma unroll
        for (int ks = 0; ks < 8; ks++) {
            qa[ks][0] = f2tf(q0[8 * ks + t]     * SCALE_);
            qa[ks][1] = f2tf(q1[8 * ks + t]     * SCALE_);
            qa[ks][2] = f2tf(q0[8 * ks + t + 4] * SCALE_);
            qa[ks][3] = f2tf(q1[8 * ks + t + 4] * SCALE_);
        }
    }

    float o[8][4];
    #pragma unroll
    for (int nt = 0; nt < 8; nt++)
        #pragma unroll
        for (int r = 0; r < 4; r++) o[nt][r] = 0.f;
    float m0 = -1e30f, m1 = -1e30f, l0 = 0.f, l1 = 0.f;

    // --- prefetch kb=0 ---
    float4 ka[2][2], va[2][2];
    #pragma unroll
    for (int i = 0; i < 2; i++) {
        int kr = krr + 32 * i;
        size_t kb_ = ((size_t)(b * S_ + kr) * 3) * DIM_ + h * HD_ + kc8 + DIM_;
        ka[i][0] = *(const float4*)&g_qkv[kb_];
        ka[i][1] = *(const float4*)&g_qkv[kb_ + 4];
        int pr = vpr + 16 * i;
        int vr = ((pr >> 2) << 3) + (pr & 3);
        size_t vb_ = ((size_t)(b * S_ + vr) * 3) * DIM_ + h * HD_ + vc4 + 2 * DIM_;
        va[i][0] = *(const float4*)&g_qkv[vb_];
        va[i][1] = *(const float4*)&g_qkv[vb_ + (size_t)4 * 3 * DIM_];
    }

    for (int kb = 0; kb < S_ / 64; kb++) {
        __syncthreads();   // prev-iter QK/PV smem reads done
        // store prefetched tile (tf32, k-pair packed)
        #pragma unroll
        for (int i = 0; i < 2; i++) {
            int kr = krr + 32 * i;
            float k0[4] = {ka[i][0].x, ka[i][0].y, ka[i][0].z, ka[i][0].w};
            float k1[4] = {ka[i][1].x, ka[i][1].y, ka[i][1].z, ka[i][1].w};
            #pragma unroll
            for (int j = 0; j < 4; j++)
                Ks2[kr * KS2 + (kc8 >> 1) + j] = make_float2(tff(k0[j]), tff(k1[j]));
            int pr = vpr + 16 * i;
            float v0[4] = {va[i][0].x, va[i][0].y, va[i][0].z, va[i][0].w};
            float v1[4] = {va[i][1].x, va[i][1].y, va[i][1].z, va[i][1].w};
            #pragma unroll
            for (int j = 0; j < 4; j++)
                Vs2[pr * VS2 + vc4 + j] = make_float2(tff(v0[j]), tff(v1[j]));
        }
        __syncthreads();

        // prefetch next tile
        if (kb + 1 < S_ / 64) {
            #pragma unroll
            for (int i = 0; i < 2; i++) {
                int kr = krr + 32 * i;
                size_t kb_ = ((size_t)(b * S_ + (kb + 1) * 64 + kr) * 3) * DIM_ + h * HD_ + kc8 + DIM_;
                ka[i][0] = *(const float4*)&g_qkv[kb_];
                ka[i][1] = *(const float4*)&g_qkv[kb_ + 4];
                int pr = vpr + 16 * i;
                int vr = ((pr >> 2) << 3) + (pr & 3);
                size_t vb_ = ((size_t)(b * S_ + (kb + 1) * 64 + vr) * 3) * DIM_ + h * HD_ + vc4 + 2 * DIM_;
                va[i][0] = *(const float4*)&g_qkv[vb_];
                va[i][1] = *(const float4*)&g_qkv[vb_ + (size_t)4 * 3 * DIM_];
            }
        }

        // --- S = Q @ K^T ---
        float s[8][4];
        #pragma unroll
        for (int nt = 0; nt < 8; nt++)
            #pragma unroll
            for (int r = 0; r < 4; r++) s[nt][r] = 0.f;

        #pragma unroll
        for (int ks = 0; ks < 8; ks++) {
            #pragma unroll
            for (int nt = 0; nt < 8; nt++) {
                float2 kv = Ks2[(nt * 8 + g) * KS2 + 4 * ks + t];
                unsigned bf[2] = {__float_as_uint(kv.x), __float_as_uint(kv.y)};
                MMA_TF32(s[nt], qa[ks], bf);
            }
        }

        // --- online softmax ---
        float mx0 = -1e30f, mx1 = -1e30f;
        #pragma unroll
        for (int nt = 0; nt < 8; nt++) {
            mx0 = fmaxf(mx0, fmaxf(s[nt][0], s[nt][1]));
            mx1 = fmaxf(mx1, fmaxf(s[nt][2], s[nt][3]));
        }
        mx0 = fmaxf(mx0, __shfl_xor_sync(0xffffffffu, mx0, 1));
        mx0 = fmaxf(mx0, __shfl_xor_sync(0xffffffffu, mx0, 2));
        mx1 = fmaxf(mx1, __shfl_xor_sync(0xffffffffu, mx1, 1));
        mx1 = fmaxf(mx1, __shfl_xor_sync(0xffffffffu, mx1, 2));

        float mn0 = fmaxf(m0, mx0), mn1 = fmaxf(m1, mx1);
        float al0 = __expf(m0 - mn0), al1 = __expf(m1 - mn1);

        float ls0 = 0.f, ls1 = 0.f;
        #pragma unroll
        for (int nt = 0; nt < 8; nt++) {
            float p0 = __expf(s[nt][0] - mn0);
            float p1 = __expf(s[nt][1] - mn0);
            float p2 = __expf(s[nt][2] - mn1);
            float p3 = __expf(s[nt][3] - mn1);
            ls0 += p0 + p1;
            ls1 += p2 + p3;
            // Pw2[k][g] = (P[g][k], P[g+8][k])
            Pw2[(nt * 8 + 2 * t)     * PS2 + g] = make_float2(tff(p0), tff(p2));
            Pw2[(nt * 8 + 2 * t + 1) * PS2 + g] = make_float2(tff(p1), tff(p3));
        }
        ls0 += __shfl_xor_sync(0xffffffffu, ls0, 1);
        ls0 += __shfl_xor_sync(0xffffffffu, ls0, 2);
        ls1 += __shfl_xor_sync(0xffffffffu, ls1, 1);
        ls1 += __shfl_xor_sync(0xffffffffu, ls1, 2);
        l0 = l0 * al0 + ls0;  m0 = mn0;
        l1 = l1 * al1 + ls1;  m1 = mn1;

        #pragma unroll
        for (int nt = 0; nt < 8; nt++) {
            o[nt][0] *= al0; o[nt][1] *= al0;
            o[nt][2] *= al1; o[nt][3] *= al1;
        }

        __syncwarp();   // P strip is warp-private

        // --- O += P @ V ---
        #pragma unroll
        for (int ks = 0; ks < 8; ks++) {
            float2 a01 = Pw2[(8 * ks + t)     * PS2 + g];
            float2 a23 = Pw2[(8 * ks + t + 4) * PS2 + g];
            unsigned pa4[4] = {__float_as_uint(a01.x), __float_as_uint(a01.y),
                               __float_as_uint(a23.x), __float_as_uint(a23.y)};
            #pragma unroll
            for (int nt = 0; nt < 8; nt++) {
                float2 vv = Vs2[(4 * ks + t) * VS2 + nt * 8 + g];
                unsigned bf[2] = {__float_as_uint(vv.x), __float_as_uint(vv.y)};
                MMA_TF32(o[nt], pa4, bf);
            }
        }
        __syncwarp();   // PV reads done before next-iter P overwrite
    }

    // --- normalize + store ---
    float inv0 = 1.f / l0, inv1 = 1.f / l1;
    size_t row0 = (size_t)(b * S_ + qb * 128 + wm + g) * DIM_ + h * HD_;
    size_t row1 = row0 + (size_t)8 * DIM_;
    #pragma unroll
    for (int nt = 0; nt < 8; nt++) {
        *(float2*)&g_attn[row0 + nt * 8 + 2 * t] =
            make_float2(o[nt][0] * inv0, o[nt][1] * inv0);
        *(float2*)&g_attn[row1 + nt * 8 + 2 * t] =
            make_float2(o[nt][2] * inv1, o[nt][3] * inv1);
    }
}

// ---------------------------------------------------------------------------
extern "C" void kernel_launch(void* const* d_in, const int* in_sizes, int n_in,
                              void* d_out, int out_size)
{
    const float* x     = (const float*)d_in[0];   // (2, 2048, 1024)
    const float* Wqkv  = (const float*)d_in[1];   // (1024, 3072)
    const float* Wproj = (const float*)d_in[2];   // (1024, 1024)
    float* out = (float*)d_out;                   // (2, 2048, 1024)

    float* qkv_ptr  = nullptr;
    float* attn_ptr = nullptr;
    cudaGetSymbolAddress((void**)&qkv_ptr,  g_qkv);
    cudaGetSymbolAddress((void**)&attn_ptr, g_attn);

    const int M = B_ * S_;   // 4096

    cudaFuncSetAttribute(flash4_kernel,
                         cudaFuncAttributeMaxDynamicSharedMemorySize, FL_SMEM);

    // 1) qkv = x @ Wqkv                (4096 x 3072, K=1024), tf32
    tgemm128_kernel<<<dim3(3 * DIM_ / 128, M / 128), 256>>>(
        x, Wqkv, qkv_ptr, M, 3 * DIM_, DIM_);

    // 2) attention, tf32 tensor cores (k-pair packed)
    flash4_kernel<<<dim3(S_ / 128, H_, B_), 256, FL_SMEM>>>();

    // 3) out = attn @ Wproj            (4096 x 1024, K=1024), tf32
    tgemm128_kernel<<<dim3(DIM_ / 128, M / 128), 256>>>(
        attn_ptr, Wproj, out, M, DIM_, DIM_);
}

// round 14
// speedup vs baseline: 1.7180x; 1.7180x over previous
#include <cuda_runtime.h>

#define B_   2
#define S_   2048
#define H_   16
#define HD_  64
#define DIM_ 1024
#define SCALE_ 0.125f

// Scratch (allocation-free rule: __device__ globals)
__device__ float g_qkv[(size_t)B_ * S_ * 3 * DIM_];   // 50.3 MB
__device__ float g_attn[(size_t)B_ * S_ * DIM_];      // 16.8 MB

__device__ __forceinline__ unsigned f2tf(float x) {
    unsigned r;
    asm("cvt.rna.tf32.f32 %0, %1;" : "=r"(r) : "f"(x));
    return r;
}
__device__ __forceinline__ float tff(float x) {
    return __uint_as_float(f2tf(x));
}

#define MMA_TF32(c, a, b)                                                  \
    asm volatile("mma.sync.aligned.m16n8k8.row.col.f32.tf32.tf32.f32 "     \
                 "{%0,%1,%2,%3}, {%4,%5,%6,%7}, {%8,%9}, {%0,%1,%2,%3};"   \
                 : "+f"(c[0]), "+f"(c[1]), "+f"(c[2]), "+f"(c[3])          \
                 : "r"(a[0]), "r"(a[1]), "r"(a[2]), "r"(a[3]),             \
                   "r"(b[0]), "r"(b[1]))

// ---------------------------------------------------------------------------
// TF32 tensor-core GEMM v2 (FROZEN — clock canary): 128x128 tile, BK=16,
// 8 warps, k-pair packed smem, 2-stage double buffer.
// ---------------------------------------------------------------------------
#define P_ST 132

__global__ void __launch_bounds__(256, 2) tgemm128_kernel(
    const float* __restrict__ A, const float* __restrict__ Bm,
    float* __restrict__ C, int M, int N, int K)
{
    __shared__ float2 As2[2][8 * P_ST];
    __shared__ float2 Bs2[2][8 * P_ST];

    const int tid  = threadIdx.x;
    const int lane = tid & 31;
    const int warp = tid >> 5;
    const int g    = lane >> 2;
    const int t    = lane & 3;
    const int wm   = (warp & 1) * 64;
    const int wn   = (warp >> 1) * 32;
    const int bm   = blockIdx.y * 128;
    const int bn   = blockIdx.x * 128;

    const int am = tid >> 1;
    const int ah = tid & 1;
    const int kk6 = tid >> 5;
    const int kk  = ((kk6 >> 2) << 3) + (kk6 & 3);
    const int n4  = (tid & 31) << 2;

    const float* Arow = A + (size_t)(bm + am) * K + 8 * ah;
    const float* Bb   = Bm + bn + n4;

    float c[4][4][4];
    #pragma unroll
    for (int mi = 0; mi < 4; mi++)
        #pragma unroll
        for (int ni = 0; ni < 4; ni++)
            #pragma unroll
            for (int r = 0; r < 4; r++) c[mi][ni][r] = 0.f;

    float4 ra0, ra1, rb0, rb1;

    ra0 = *(const float4*)&Arow[0];
    ra1 = *(const float4*)&Arow[4];
    rb0 = *(const float4*)&Bb[(size_t)kk * N];
    rb1 = *(const float4*)&Bb[(size_t)(kk + 4) * N];

    {
        float a0[4] = {ra0.x, ra0.y, ra0.z, ra0.w};
        float a1[4] = {ra1.x, ra1.y, ra1.z, ra1.w};
        #pragma unroll
        for (int j = 0; j < 4; j++)
            As2[0][(4 * ah + j) * P_ST + am] = make_float2(tff(a0[j]), tff(a1[j]));
        float b0[4] = {rb0.x, rb0.y, rb0.z, rb0.w};
        float b1[4] = {rb1.x, rb1.y, rb1.z, rb1.w};
        #pragma unroll
        for (int j = 0; j < 4; j++)
            Bs2[0][kk6 * P_ST + n4 + j] = make_float2(tff(b0[j]), tff(b1[j]));
    }
    __syncthreads();

    int s = 0;
    for (int k0 = 0; k0 < K; k0 += 16) {
        const bool has_next = (k0 + 16 < K);
        if (has_next) {
            ra0 = *(const float4*)&Arow[k0 + 16];
            ra1 = *(const float4*)&Arow[k0 + 20];
            rb0 = *(const float4*)&Bb[(size_t)(k0 + 16 + kk) * N];
            rb1 = *(const float4*)&Bb[(size_t)(k0 + 20 + kk) * N];
        }

        #pragma unroll
        for (int ks = 0; ks < 2; ks++) {
            const int pb = 4 * ks + t;
            unsigned a[4][4], b[4][2];
            #pragma unroll
            for (int mi = 0; mi < 4; mi++) {
                int m0 = wm + mi * 16 + g;
                float2 v  = As2[s][pb * P_ST + m0];
                float2 v2 = As2[s][pb * P_ST + m0 + 8];
                a[mi][0] = __float_as_uint(v.x);
                a[mi][1] = __float_as_uint(v2.x);
                a[mi][2] = __float_as_uint(v.y);
                a[mi][3] = __float_as_uint(v2.y);
            }
            #pragma unroll
            for (int ni = 0; ni < 4; ni++) {
                int n0 = wn + ni * 8 + g;
                float2 w = Bs2[s][pb * P_ST + n0];
                b[ni][0] = __float_as_uint(w.x);
                b[ni][1] = __float_as_uint(w.y);
            }
            #pragma unroll
            for (int mi = 0; mi < 4; mi++)
                #pragma unroll
                for (int ni = 0; ni < 4; ni++)
                    MMA_TF32(c[mi][ni], a[mi], b[ni]);
        }

        if (has_next) {
            float a0[4] = {ra0.x, ra0.y, ra0.z, ra0.w};
            float a1[4] = {ra1.x, ra1.y, ra1.z, ra1.w};
            #pragma unroll
            for (int j = 0; j < 4; j++)
                As2[s ^ 1][(4 * ah + j) * P_ST + am] = make_float2(tff(a0[j]), tff(a1[j]));
            float b0[4] = {rb0.x, rb0.y, rb0.z, rb0.w};
            float b1[4] = {rb1.x, rb1.y, rb1.z, rb1.w};
            #pragma unroll
            for (int j = 0; j < 4; j++)
                Bs2[s ^ 1][kk6 * P_ST + n4 + j] = make_float2(tff(b0[j]), tff(b1[j]));
            __syncthreads();
        }
        s ^= 1;
    }

    #pragma unroll
    for (int mi = 0; mi < 4; mi++) {
        int row = bm + wm + mi * 16 + g;
        #pragma unroll
        for (int ni = 0; ni < 4; ni++) {
            int col = bn + wn + ni * 8 + 2 * t;
            *(float2*)&C[(size_t)row * N + col] =
                make_float2(c[mi][ni][0], c[mi][ni][1]);
            *(float2*)&C[(size_t)(row + 8) * N + col] =
                make_float2(c[mi][ni][2], c[mi][ni][3]);
        }
    }
}

// ---------------------------------------------------------------------------
// Flash attention v5 = proven flash3 layouts (all smem access <= 2-way)
// + double-buffered K/V tiles -> ONE __syncthreads per kb iteration.
// CTA = 128 q-rows, 8 warps, warp owns m16 strip. tf32 m16n8k8 MMAs.
// K stride 68 (QK b-frag banks 4g+t, CF). V stride 72 (PV b-frag banks
// 8t+g, CF). P per-warp strip stride 68 (pa-frag banks 4g+t, CF).
// ---------------------------------------------------------------------------
#define KS_ST 68
#define VS_ST 72
#define PS_ST 68
#define KS_SZ (64 * KS_ST)               // 4352 floats per stage
#define VS_SZ (64 * VS_ST)               // 4608 floats per stage
#define FL_SMEM ((2 * KS_SZ + 2 * VS_SZ + 128 * PS_ST) * 4)   // 106496 B

__global__ void __launch_bounds__(256) flash5_kernel()
{
    extern __shared__ float sm[];
    float* Ps = sm + 2 * KS_SZ + 2 * VS_SZ;   // [128][68] warp-private strips

    const int tid  = threadIdx.x;
    const int lane = tid & 31;
    const int warp = tid >> 5;
    const int g    = lane >> 2;
    const int t    = lane & 3;
    const int wm   = warp << 4;
    const int qb   = blockIdx.x;
    const int h    = blockIdx.y;
    const int b    = blockIdx.z;

    // --- Q fragments in registers (tf32, scale folded) ---
    unsigned qa[8][4];
    {
        const float* q0 = g_qkv + ((size_t)(b * S_ + qb * 128 + wm + g) * 3) * DIM_ + h * HD_;
        const float* q1 = q0 + (size_t)8 * 3 * DIM_;
        #pragma unroll
        for (int ks = 0; ks < 8; ks++) {
            qa[ks][0] = f2tf(q0[8 * ks + t]     * SCALE_);
            qa[ks][1] = f2tf(q1[8 * ks + t]     * SCALE_);
            qa[ks][2] = f2tf(q0[8 * ks + t + 4] * SCALE_);
            qa[ks][3] = f2tf(q1[8 * ks + t + 4] * SCALE_);
        }
    }

    float o[8][4];
    #pragma unroll
    for (int nt = 0; nt < 8; nt++)
        #pragma unroll
        for (int r = 0; r < 4; r++) o[nt][r] = 0.f;
    float m0 = -1e30f, m1 = -1e30f, l0 = 0.f, l1 = 0.f;

    // --- prefetch kb=0 and store to stage 0 ---
    float4 kr[4], vr[4];
    #pragma unroll
    for (int i = 0; i < 4; i++) {
        int f = (i << 8) + tid;
        int r = f >> 4, c = (f & 15) << 2;
        size_t base = ((size_t)(b * S_ + r) * 3) * DIM_ + h * HD_ + c;
        kr[i] = *(const float4*)&g_qkv[base + DIM_];
        vr[i] = *(const float4*)&g_qkv[base + 2 * DIM_];
    }
    #pragma unroll
    for (int i = 0; i < 4; i++) {
        int f = (i << 8) + tid;
        int r = f >> 4, c = (f & 15) << 2;
        *(float4*)&sm[r * KS_ST + c] =
            make_float4(tff(kr[i].x), tff(kr[i].y), tff(kr[i].z), tff(kr[i].w));
        *(float4*)&sm[2 * KS_SZ + r * VS_ST + c] =
            make_float4(tff(vr[i].x), tff(vr[i].y), tff(vr[i].z), tff(vr[i].w));
    }
    __syncthreads();

    int s = 0;
    for (int kb = 0; kb < S_ / 64; kb++) {
        const bool has_next = (kb + 1 < S_ / 64);
        float* Ksc = sm + s * KS_SZ;
        float* Vsc = sm + 2 * KS_SZ + s * VS_SZ;

        // prefetch next tile into registers (covers whole compute phase)
        if (has_next) {
            #pragma unroll
            for (int i = 0; i < 4; i++) {
                int f = (i << 8) + tid;
                int r = f >> 4, c = (f & 15) << 2;
                size_t base = ((size_t)(b * S_ + (kb + 1) * 64 + r) * 3) * DIM_ + h * HD_ + c;
                kr[i] = *(const float4*)&g_qkv[base + DIM_];
                vr[i] = *(const float4*)&g_qkv[base + 2 * DIM_];
            }
        }

        // --- S = Q @ K^T ---
        float sc[8][4];
        #pragma unroll
        for (int nt = 0; nt < 8; nt++)
            #pragma unroll
            for (int r = 0; r < 4; r++) sc[nt][r] = 0.f;

        #pragma unroll
        for (int ks = 0; ks < 8; ks++) {
            #pragma unroll
            for (int nt = 0; nt < 8; nt++) {
                unsigned bf[2];
                const float* krow = &Ksc[(nt * 8 + g) * KS_ST + 8 * ks + t];
                bf[0] = __float_as_uint(krow[0]);
                bf[1] = __float_as_uint(krow[4]);
                MMA_TF32(sc[nt], qa[ks], bf);
            }
        }

        // --- online softmax (rows wm+g and wm+g+8; reduce over t-lanes) ---
        float mx0 = -1e30f, mx1 = -1e30f;
        #pragma unroll
        for (int nt = 0; nt < 8; nt++) {
            mx0 = fmaxf(mx0, fmaxf(sc[nt][0], sc[nt][1]));
            mx1 = fmaxf(mx1, fmaxf(sc[nt][2], sc[nt][3]));
        }
        mx0 = fmaxf(mx0, __shfl_xor_sync(0xffffffffu, mx0, 1));
        mx0 = fmaxf(mx0, __shfl_xor_sync(0xffffffffu, mx0, 2));
        mx1 = fmaxf(mx1, __shfl_xor_sync(0xffffffffu, mx1, 1));
        mx1 = fmaxf(mx1, __shfl_xor_sync(0xffffffffu, mx1, 2));

        float mn0 = fmaxf(m0, mx0), mn1 = fmaxf(m1, mx1);
        float al0 = __expf(m0 - mn0), al1 = __expf(m1 - mn1);

        float* Pw = Ps + wm * PS_ST;
        float ls0 = 0.f, ls1 = 0.f;
        #pragma unroll
        for (int nt = 0; nt < 8; nt++) {
            float p0 = __expf(sc[nt][0] - mn0);
            float p1 = __expf(sc[nt][1] - mn0);
            float p2 = __expf(sc[nt][2] - mn1);
            float p3 = __expf(sc[nt][3] - mn1);
            ls0 += p0 + p1;
            ls1 += p2 + p3;
            *(float2*)&Pw[g * PS_ST + nt * 8 + 2 * t] =
                make_float2(tff(p0), tff(p1));
            *(float2*)&Pw[(g + 8) * PS_ST + nt * 8 + 2 * t] =
                make_float2(tff(p2), tff(p3));
        }
        ls0 += __shfl_xor_sync(0xffffffffu, ls0, 1);
        ls0 += __shfl_xor_sync(0xffffffffu, ls0, 2);
        ls1 += __shfl_xor_sync(0xffffffffu, ls1, 1);
        ls1 += __shfl_xor_sync(0xffffffffu, ls1, 2);
        l0 = l0 * al0 + ls0;  m0 = mn0;
        l1 = l1 * al1 + ls1;  m1 = mn1;

        #pragma unroll
        for (int nt = 0; nt < 8; nt++) {
            o[nt][0] *= al0; o[nt][1] *= al0;
            o[nt][2] *= al1; o[nt][3] *= al1;
        }

        __syncwarp();   // P strip is warp-private

        // --- O += P @ V ---
        #pragma unroll
        for (int ks = 0; ks < 8; ks++) {
            unsigned pa4[4];
            pa4[0] = __float_as_uint(Pw[g * PS_ST + 8 * ks + t]);
            pa4[1] = __float_as_uint(Pw[(g + 8) * PS_ST + 8 * ks + t]);
            pa4[2] = __float_as_uint(Pw[g * PS_ST + 8 * ks + t + 4]);
            pa4[3] = __float_as_uint(Pw[(g + 8) * PS_ST + 8 * ks + t + 4]);
            #pragma unroll
            for (int nt = 0; nt < 8; nt++) {
                unsigned bf[2];
                bf[0] = __float_as_uint(Vsc[(8 * ks + t) * VS_ST + nt * 8 + g]);
                bf[1] = __float_as_uint(Vsc[(8 * ks + t + 4) * VS_ST + nt * 8 + g]);
                MMA_TF32(o[nt], pa4, bf);
            }
        }
        __syncwarp();   // PV reads done before next-iter P overwrite

        // --- store next tile into the OTHER stage, then single barrier ---
        if (has_next) {
            float* Ksn = sm + (s ^ 1) * KS_SZ;
            float* Vsn = sm + 2 * KS_SZ + (s ^ 1) * VS_SZ;
            #pragma unroll
            for (int i = 0; i < 4; i++) {
                int f = (i << 8) + tid;
                int r = f >> 4, c = (f & 15) << 2;
                *(float4*)&Ksn[r * KS_ST + c] =
                    make_float4(tff(kr[i].x), tff(kr[i].y), tff(kr[i].z), tff(kr[i].w));
                *(float4*)&Vsn[r * VS_ST + c] =
                    make_float4(tff(vr[i].x), tff(vr[i].y), tff(vr[i].z), tff(vr[i].w));
            }
            __syncthreads();
        }
        s ^= 1;
    }

    // --- normalize + store ---
    float inv0 = 1.f / l0, inv1 = 1.f / l1;
    size_t row0 = (size_t)(b * S_ + qb * 128 + wm + g) * DIM_ + h * HD_;
    size_t row1 = row0 + (size_t)8 * DIM_;
    #pragma unroll
    for (int nt = 0; nt < 8; nt++) {
        *(float2*)&g_attn[row0 + nt * 8 + 2 * t] =
            make_float2(o[nt][0] * inv0, o[nt][1] * inv0);
        *(float2*)&g_attn[row1 + nt * 8 + 2 * t] =
            make_float2(o[nt][2] * inv1, o[nt][3] * inv1);
    }
}

// ---------------------------------------------------------------------------
extern "C" void kernel_launch(void* const* d_in, const int* in_sizes, int n_in,
                              void* d_out, int out_size)
{
    const float* x     = (const float*)d_in[0];   // (2, 2048, 1024)
    const float* Wqkv  = (const float*)d_in[1];   // (1024, 3072)
    const float* Wproj = (const float*)d_in[2];   // (1024, 1024)
    float* out = (float*)d_out;                   // (2, 2048, 1024)

    float* qkv_ptr  = nullptr;
    float* attn_ptr = nullptr;
    cudaGetSymbolAddress((void**)&qkv_ptr,  g_qkv);
    cudaGetSymbolAddress((void**)&attn_ptr, g_attn);

    const int M = B_ * S_;   // 4096

    cudaFuncSetAttribute(flash5_kernel,
                         cudaFuncAttributeMaxDynamicSharedMemorySize, FL_SMEM);

    // 1) qkv = x @ Wqkv                (4096 x 3072, K=1024), tf32
    tgemm128_kernel<<<dim3(3 * DIM_ / 128, M / 128), 256>>>(
        x, Wqkv, qkv_ptr, M, 3 * DIM_, DIM_);

    // 2) attention, tf32 tensor cores (double-buffered K/V, 1 barrier/iter)
    flash5_kernel<<<dim3(S_ / 128, H_, B_), 256, FL_SMEM>>>();

    // 3) out = attn @ Wproj            (4096 x 1024, K=1024), tf32
    tgemm128_kernel<<<dim3(DIM_ / 128, M / 128), 256>>>(
        attn_ptr, Wproj, out, M, DIM_, DIM_);
}